// round 6
// baseline (speedup 1.0000x reference)
#include <cuda_runtime.h>

#define COLS 8192
#define COLS4 2048            // float4 per row
#define ROWS 1024
#define SCALE 0.75f
#define RPB 2
#define NBLK (ROWS / RPB)     // 512 blocks

// Scratch (no allocation allowed). 32B-aligned for LDG.256.
__device__ __align__(32) float g_wtotal[COLS];

// LDG.256 + L2 evict_last (x stream: keep L2-resident across graph replays).
__device__ __forceinline__ void ldg256_el(const float* p, float4& a, float4& b) {
    unsigned r0, r1, r2, r3, r4, r5, r6, r7;
    asm("ld.global.nc.L2::evict_last.v8.b32 {%0,%1,%2,%3,%4,%5,%6,%7}, [%8];"
        : "=r"(r0), "=r"(r1), "=r"(r2), "=r"(r3),
          "=r"(r4), "=r"(r5), "=r"(r6), "=r"(r7)
        : "l"(p));
    a.x = __uint_as_float(r0); a.y = __uint_as_float(r1);
    a.z = __uint_as_float(r2); a.w = __uint_as_float(r3);
    b.x = __uint_as_float(r4); b.y = __uint_as_float(r5);
    b.z = __uint_as_float(r6); b.w = __uint_as_float(r7);
}

// Plain LDG.256 (w: small, L2-hot).
__device__ __forceinline__ void ldg256(const float* p, float4& a, float4& b) {
    unsigned r0, r1, r2, r3, r4, r5, r6, r7;
    asm("ld.global.nc.v8.b32 {%0,%1,%2,%3,%4,%5,%6,%7}, [%8];"
        : "=r"(r0), "=r"(r1), "=r"(r2), "=r"(r3),
          "=r"(r4), "=r"(r5), "=r"(r6), "=r"(r7)
        : "l"(p));
    a.x = __uint_as_float(r0); a.y = __uint_as_float(r1);
    a.z = __uint_as_float(r2); a.w = __uint_as_float(r3);
    b.x = __uint_as_float(r4); b.y = __uint_as_float(r5);
    b.z = __uint_as_float(r6); b.w = __uint_as_float(r7);
}

// Kernel 1: w_total[c] = sum_g wsums[g][c]. Grid 64 x 256 threads.
__global__ __launch_bounds__(256) void reduce_w_kernel(const float* __restrict__ wsums) {
    const int lcol  = threadIdx.x & 31;
    const int chunk = threadIdx.x >> 5;               // 0..7, 4 groups each
    const int c4    = blockIdx.x * 32 + lcol;

    const float4* __restrict__ w4 = reinterpret_cast<const float4*>(wsums);
    float4 s = make_float4(0.f, 0.f, 0.f, 0.f);
#pragma unroll
    for (int g = 0; g < 4; ++g) {
        float4 v = w4[(size_t)(chunk * 4 + g) * COLS4 + c4];
        s.x += v.x; s.y += v.y; s.z += v.z; s.w += v.w;
    }

    __shared__ float4 sm[8][32];
    sm[chunk][lcol] = s;
    __syncthreads();

    if (threadIdx.x < 32) {
        float4 r = make_float4(0.f, 0.f, 0.f, 0.f);
#pragma unroll
        for (int c = 0; c < 8; ++c) {
            float4 v = sm[c][threadIdx.x];
            r.x += v.x; r.y += v.y; r.z += v.z; r.w += v.w;
        }
        reinterpret_cast<float4*>(g_wtotal)[c4] = r;
    }
}

// Kernel 2: 2 rows per block, BOTH rows' loads batched before any consumption
// (8 independent LDG.256 = 256B in flight per thread). w lives in SMEM,
// de-interleaved so the FMA-phase LDS.128 is conflict-free.
__global__ __launch_bounds__(256, 3) void dot2_kernel(const float* __restrict__ x,
                                                      float* __restrict__ out) {
    __shared__ float4 ws[COLS4];          // 32 KB
    __shared__ float red[RPB][8];

    const int t = threadIdx.x;
    const int row0 = blockIdx.x * RPB;
    const float* __restrict__ xr0 = x + (size_t)row0 * COLS;
    const float* __restrict__ xr1 = xr0 + COLS;

    // x: issue all 8 LDG.256 first so they own the head of the LSU queue.
    float4 a[8], b[8];
#pragma unroll
    for (int i = 0; i < 4; ++i)
        ldg256_el(xr0 + (size_t)(i * 256 + t) * 8, a[2 * i], a[2 * i + 1]);
#pragma unroll
    for (int i = 0; i < 4; ++i)
        ldg256_el(xr1 + (size_t)(i * 256 + t) * 8, b[2 * i], b[2 * i + 1]);

    // w -> smem (L2 hits; latency hidden under the x waits).
    // De-interleave so slot j of a/b pairs with ws[j*256 + t].
#pragma unroll
    for (int i = 0; i < 4; ++i) {
        float4 w0, w1;
        ldg256(g_wtotal + (size_t)(i * 256 + t) * 8, w0, w1);
        ws[(2 * i) * 256 + t]     = w0;
        ws[(2 * i + 1) * 256 + t] = w1;
    }
    __syncthreads();

    float s0 = 0.f, s0b = 0.f, s1 = 0.f, s1b = 0.f;
#pragma unroll
    for (int j = 0; j < 8; j += 2) {
        const float4 w0 = ws[j * 256 + t];
        const float4 w1 = ws[(j + 1) * 256 + t];
        s0  = fmaf(a[j].x,     w0.x, s0);  s0  = fmaf(a[j].y,     w0.y, s0);
        s0  = fmaf(a[j].z,     w0.z, s0);  s0  = fmaf(a[j].w,     w0.w, s0);
        s0b = fmaf(a[j + 1].x, w1.x, s0b); s0b = fmaf(a[j + 1].y, w1.y, s0b);
        s0b = fmaf(a[j + 1].z, w1.z, s0b); s0b = fmaf(a[j + 1].w, w1.w, s0b);
        s1  = fmaf(b[j].x,     w0.x, s1);  s1  = fmaf(b[j].y,     w0.y, s1);
        s1  = fmaf(b[j].z,     w0.z, s1);  s1  = fmaf(b[j].w,     w0.w, s1);
        s1b = fmaf(b[j + 1].x, w1.x, s1b); s1b = fmaf(b[j + 1].y, w1.y, s1b);
        s1b = fmaf(b[j + 1].z, w1.z, s1b); s1b = fmaf(b[j + 1].w, w1.w, s1b);
    }
    float sr0 = s0 + s0b;
    float sr1 = s1 + s1b;

    // Deferred reduction for both rows.
#pragma unroll
    for (int o = 16; o > 0; o >>= 1) {
        sr0 += __shfl_xor_sync(0xFFFFFFFFu, sr0, o);
        sr1 += __shfl_xor_sync(0xFFFFFFFFu, sr1, o);
    }
    const int wid = t >> 5, lid = t & 31;
    if (lid == 0) { red[0][wid] = sr0; red[1][wid] = sr1; }
    __syncthreads();

    if (t < 16) {
        const int r = t >> 3, w8 = t & 7;
        float v = red[r][w8];
#pragma unroll
        for (int o = 4; o > 0; o >>= 1)
            v += __shfl_xor_sync(0xFFFFu, v, o);
        if (w8 == 0) out[row0 + r] = v * SCALE;
    }
}

extern "C" void kernel_launch(void* const* d_in, const int* in_sizes, int n_in,
                              void* d_out, int out_size) {
    const float* x     = (const float*)d_in[0];  // [1024, 8192] f32
    const float* wsums = (const float*)d_in[1];  // [32, 8192] f32
    float* out         = (float*)d_out;          // [1024, 1] f32

    reduce_w_kernel<<<COLS4 / 32, 256>>>(wsums);
    dot2_kernel<<<NBLK, 256>>>(x, out);
}